// round 1
// baseline (speedup 1.0000x reference)
#include <cuda_runtime.h>
#include <stdint.h>

// ---------------------------------------------------------------------------
// extract_high_freq via db4 wavelet, images: [96][512][512] fp32
//   lo_w, hi_w       = row-DWT(data)                (m = 259 per row)
//   lo_rec           = lo_w + Bcol(lh)              (lh = col-detail of lo_w)
//   hi_rec           = 2 * hi_w                     (perfect reconstruction)
//   out              = row-IDWT(lo_rec, hi_rec)
// ---------------------------------------------------------------------------

#define N     512          // signal length per axis
#define M     259          // dwt coeff length: (512+7)/2
#define MP    288          // padded stride (288*4 = 1152 B, 128B-aligned rows)
#define NIMG  96           // 32*3 images
#define NROWS (NIMG * N)   // 49152

// db4 dec_lo taps
#define DL0 (-0.010597401784997278f)
#define DL1 ( 0.032883011666982945f)
#define DL2 ( 0.030841381835986965f)
#define DL3 (-0.18703481171888114f)
#define DL4 (-0.02798376941698385f)
#define DL5 ( 0.6308807679295904f)
#define DL6 ( 0.7148465705525415f)
#define DL7 ( 0.23037781330885523f)

// REC_LO[j] = DEC_LO[7-j] ; REC_HI[j] = DEC_HI[7-j] = (-1)^j * DEC_LO[j]
#define REC_LO_INIT { DL7,  DL6,  DL5,  DL4,  DL3,  DL2,  DL1,  DL0 }
#define REC_HI_INIT { DL0, -DL1,  DL2, -DL3,  DL4, -DL5,  DL6, -DL7 }

// Scratch (device globals: allocation-free rule)
__device__ float g_lo   [(size_t)NIMG * N * MP];
__device__ float g_hi   [(size_t)NIMG * N * MP];
__device__ float g_lorec[(size_t)NIMG * N * MP];

// symmetric extension index map for ext[e] = x[mir(e-6)], signal length N
__device__ __forceinline__ int mirN(int i) {
    if (i < 0)  i = -1 - i;
    if (i >= N) i = 2 * N - 1 - i;
    return i;
}

// ---------------------------------------------------------------------------
// K1: row DWT.  One block per row.  a[k] = sum_j ext[2k+j]*REC_LO[j], d likewise
// ---------------------------------------------------------------------------
__global__ void __launch_bounds__(256) k_row_dwt(const float* __restrict__ x)
{
    __shared__ float s[N];
    const int row = blockIdx.x;
    const float* xr = x + (size_t)row * N;
    s[threadIdx.x]       = xr[threadIdx.x];
    s[threadIdx.x + 256] = xr[threadIdx.x + 256];
    __syncthreads();

    const float rl[8] = REC_LO_INIT;
    const float rh[8] = REC_HI_INIT;

    float* lo = g_lo + (size_t)row * MP;
    float* hi = g_hi + (size_t)row * MP;

    for (int k = threadIdx.x; k < M; k += 256) {
        const int e0 = 2 * k - 6;
        float a = 0.f, d = 0.f;
#pragma unroll
        for (int j = 0; j < 8; ++j) {
            const float v = s[mirN(e0 + j)];
            a = fmaf(v, rl[j], a);
            d = fmaf(v, rh[j], d);
        }
        lo[k] = a;
        hi[k] = d;
    }
}

// ---------------------------------------------------------------------------
// K2: column pass on lo_w only:  lo_rec[:,c] = lo_w[:,c] + Bcol(lh[:,c])
//     lh[k] = sum_j ext[2k+j]*REC_HI[j]  (ext along rows)
//     B(d)[t] = sum_{i=0..3} d[k0+i] * REC_HI[tap(t,i)]
// 32 cols x 512 rows per block, smem stride 32 (conflict-free both phases).
// ---------------------------------------------------------------------------
__global__ void __launch_bounds__(256) k_col_fix()
{
    extern __shared__ float sm[];
    float* xs = sm;            // [N][32]
    float* ds = sm + N * 32;   // [M][32]

    const int x   = threadIdx.x;                 // 0..31 (col in tile)
    const int ty  = threadIdx.y;                 // 0..7
    const int col = blockIdx.x * 32 + x;
    const int img = blockIdx.y;
    const bool valid = (col < M);

    const float* in = g_lo + (size_t)img * N * MP;

    for (int r = ty; r < N; r += 8)
        xs[r * 32 + x] = valid ? in[(size_t)r * MP + col] : 0.f;
    __syncthreads();

    const float rh[8] = REC_HI_INIT;

    for (int k = ty; k < M; k += 8) {
        const int e0 = 2 * k - 6;
        float d = 0.f;
#pragma unroll
        for (int j = 0; j < 8; ++j)
            d = fmaf(xs[mirN(e0 + j) * 32 + x], rh[j], d);
        ds[k * 32 + x] = d;
    }
    __syncthreads();

    float* out = g_lorec + (size_t)img * N * MP;

    // t = ty + 8*i -> parity of t is parity of ty (uniform per thread)
    if (ty & 1) {
        for (int t = ty; t < N; t += 8) {
            const int k0 = (t - 1) >> 1;
            float b;
            b = ds[(k0    ) * 32 + x] * rh[7];
            b = fmaf(ds[(k0 + 1) * 32 + x], rh[5], b);
            b = fmaf(ds[(k0 + 2) * 32 + x], rh[3], b);
            b = fmaf(ds[(k0 + 3) * 32 + x], rh[1], b);
            if (valid) out[(size_t)t * MP + col] = xs[t * 32 + x] + b;
        }
    } else {
        for (int t = ty; t < N; t += 8) {
            const int k0 = t >> 1;
            float b;
            b = ds[(k0    ) * 32 + x] * rh[6];
            b = fmaf(ds[(k0 + 1) * 32 + x], rh[4], b);
            b = fmaf(ds[(k0 + 2) * 32 + x], rh[2], b);
            b = fmaf(ds[(k0 + 3) * 32 + x], rh[0], b);
            if (valid) out[(size_t)t * MP + col] = xs[t * 32 + x] + b;
        }
    }
}

// ---------------------------------------------------------------------------
// K3: row IDWT.  out = A_row(lo_rec) + B_row(2*hi_w)  (factor 2 folded into sd)
// ---------------------------------------------------------------------------
__global__ void __launch_bounds__(256) k_row_idwt(float* __restrict__ out)
{
    __shared__ float sa[M + 1];
    __shared__ float sd[M + 1];
    const int row = blockIdx.x;
    const float* ar = g_lorec + (size_t)row * MP;
    const float* dr = g_hi    + (size_t)row * MP;

    for (int k = threadIdx.x; k < M; k += 256) {
        sa[k] = ar[k];
        sd[k] = 2.f * dr[k];
    }
    __syncthreads();

    const float rl[8] = REC_LO_INIT;
    const float rh[8] = REC_HI_INIT;

    float* o = out + (size_t)row * N;
#pragma unroll
    for (int tt = 0; tt < 2; ++tt) {
        const int t = threadIdx.x + tt * 256;
        float r;
        if (t & 1) {
            const int k0 = (t - 1) >> 1;
            r =      sa[k0    ] * rl[7];
            r = fmaf(sa[k0 + 1], rl[5], r);
            r = fmaf(sa[k0 + 2], rl[3], r);
            r = fmaf(sa[k0 + 3], rl[1], r);
            r = fmaf(sd[k0    ], rh[7], r);
            r = fmaf(sd[k0 + 1], rh[5], r);
            r = fmaf(sd[k0 + 2], rh[3], r);
            r = fmaf(sd[k0 + 3], rh[1], r);
        } else {
            const int k0 = t >> 1;
            r =      sa[k0    ] * rl[6];
            r = fmaf(sa[k0 + 1], rl[4], r);
            r = fmaf(sa[k0 + 2], rl[2], r);
            r = fmaf(sa[k0 + 3], rl[0], r);
            r = fmaf(sd[k0    ], rh[6], r);
            r = fmaf(sd[k0 + 1], rh[4], r);
            r = fmaf(sd[k0 + 2], rh[2], r);
            r = fmaf(sd[k0 + 3], rh[0], r);
        }
        o[t] = r;
    }
}

// ---------------------------------------------------------------------------
extern "C" void kernel_launch(void* const* d_in, const int* in_sizes, int n_in,
                              void* d_out, int out_size)
{
    const float* data = (const float*)d_in[0];
    float* out = (float*)d_out;
    (void)in_sizes; (void)n_in; (void)out_size;

    const int k2_smem = (N * 32 + M * 32) * (int)sizeof(float);  // 98688 B
    cudaFuncSetAttribute(k_col_fix, cudaFuncAttributeMaxDynamicSharedMemorySize,
                         k2_smem);

    k_row_dwt<<<NROWS, 256>>>(data);
    k_col_fix<<<dim3((M + 31) / 32, NIMG), dim3(32, 8), k2_smem>>>();
    k_row_idwt<<<NROWS, 256>>>(out);
}

// round 2
// speedup vs baseline: 1.2955x; 1.2955x over previous
#include <cuda_runtime.h>
#include <stdint.h>

// ---------------------------------------------------------------------------
// extract_high_freq via db4 wavelet, images: [96][512][512] fp32
//   lo_w, hi_w = row-DWT(data)            (m = 259 per row)
//   lo_rec     = lo_w + Bcol(lh)          (lh = col-detail of lo_w)
//   hi_rec     = 2 * hi_w                 (perfect reconstruction)
//   out        = row-IDWT(lo_rec, hi_rec)
// ---------------------------------------------------------------------------

#define N     512
#define M     259          // (512+7)/2
#define MP    288          // padded stride, 1152 B (128B-aligned rows)
#define NIMG  96
#define NROWS (NIMG * N)

#define DL0 (-0.010597401784997278f)
#define DL1 ( 0.032883011666982945f)
#define DL2 ( 0.030841381835986965f)
#define DL3 (-0.18703481171888114f)
#define DL4 (-0.02798376941698385f)
#define DL5 ( 0.6308807679295904f)
#define DL6 ( 0.7148465705525415f)
#define DL7 ( 0.23037781330885523f)

// REC_LO[j] = DEC_LO[7-j] ; REC_HI[j] = (-1)^j * DEC_LO[j]
#define REC_LO_INIT { DL7,  DL6,  DL5,  DL4,  DL3,  DL2,  DL1,  DL0 }
#define REC_HI_INIT { DL0, -DL1,  DL2, -DL3,  DL4, -DL5,  DL6, -DL7 }

__device__ float g_lo   [(size_t)NIMG * N * MP];
__device__ float g_hi   [(size_t)NIMG * N * MP];
__device__ float g_lorec[(size_t)NIMG * N * MP];

__device__ __forceinline__ int mirN(int i) {
    if (i < 0)  i = -1 - i;
    if (i >= N) i = 2 * N - 1 - i;
    return i;
}

// ---------------------------------------------------------------------------
// K1: row DWT. 2 rows per block, 256 threads per row.
// Interior k in [3,255]: window s[2k-6 .. 2k+1] = 4 aligned float2 loads.
// ---------------------------------------------------------------------------
__global__ void __launch_bounds__(512) k_row_dwt(const float* __restrict__ x)
{
    __shared__ float2 s2[2][N / 2];
    const int ry  = threadIdx.y;              // 0..1
    const int row = blockIdx.x * 2 + ry;
    const int k   = threadIdx.x;              // 0..255

    const float2* xr = (const float2*)(x + (size_t)row * N);
    s2[ry][k] = xr[k];
    __syncthreads();

    const float rl[8] = REC_LO_INIT;
    const float rh[8] = REC_HI_INIT;
    const float* s = (const float*)s2[ry];

    float* lo = g_lo + (size_t)row * MP;
    float* hi = g_hi + (size_t)row * MP;

    if (k >= 3) {
        // fast interior path: no mirroring
        const float2 p0 = s2[ry][k - 3];
        const float2 p1 = s2[ry][k - 2];
        const float2 p2 = s2[ry][k - 1];
        const float2 p3 = s2[ry][k];
        float a, d;
        a =      p0.x * rl[0];          d =      p0.x * rh[0];
        a = fmaf(p0.y,  rl[1], a);      d = fmaf(p0.y,  rh[1], d);
        a = fmaf(p1.x,  rl[2], a);      d = fmaf(p1.x,  rh[2], d);
        a = fmaf(p1.y,  rl[3], a);      d = fmaf(p1.y,  rh[3], d);
        a = fmaf(p2.x,  rl[4], a);      d = fmaf(p2.x,  rh[4], d);
        a = fmaf(p2.y,  rl[5], a);      d = fmaf(p2.y,  rh[5], d);
        a = fmaf(p3.x,  rl[6], a);      d = fmaf(p3.x,  rh[6], d);
        a = fmaf(p3.y,  rl[7], a);      d = fmaf(p3.y,  rh[7], d);
        lo[k] = a;  hi[k] = d;
    } else {
        // left boundary (k = 0,1,2)
        const int e0 = 2 * k - 6;
        float a = 0.f, d = 0.f;
#pragma unroll
        for (int j = 0; j < 8; ++j) {
            const float v = s[mirN(e0 + j)];
            a = fmaf(v, rl[j], a);
            d = fmaf(v, rh[j], d);
        }
        lo[k] = a;  hi[k] = d;

        // right tail (k' = 256..258), handled by the same 3 threads
        const int kk = 256 + k;
        const int f0 = 2 * kk - 6;
        a = 0.f; d = 0.f;
#pragma unroll
        for (int j = 0; j < 8; ++j) {
            const float v = s[mirN(f0 + j)];
            a = fmaf(v, rl[j], a);
            d = fmaf(v, rh[j], d);
        }
        lo[kk] = a;  hi[kk] = d;
    }
}

// ---------------------------------------------------------------------------
// K2: column correction on lo_w: lo_rec[:,c] = lo_w[:,c] + Bcol(lh[:,c])
// 32 cols x 512 rows per block, 512 threads (32x16), smem stride 32.
// Step 16 preserves parity of k / t per thread -> uniform branches.
// ---------------------------------------------------------------------------
__global__ void __launch_bounds__(512) k_col_fix()
{
    extern __shared__ float sm[];
    float* xs = sm;            // [N][32]
    float* ds = sm + N * 32;   // [M][32]

    const int x   = threadIdx.x;                 // 0..31
    const int ty  = threadIdx.y;                 // 0..15
    const int col = blockIdx.x * 32 + x;
    const int img = blockIdx.y;
    const bool valid = (col < M);

    const float* in = g_lo + (size_t)img * N * MP;

#pragma unroll 4
    for (int r = ty; r < N; r += 16)
        xs[r * 32 + x] = valid ? in[(size_t)r * MP + col] : 0.f;
    __syncthreads();

    const float rh[8] = REC_HI_INIT;

#pragma unroll
    for (int k = ty; k < M; k += 16) {
        const int e0 = 2 * k - 6;
        float d;
        if (k >= 3 && k <= 255) {
            const float* p = xs + e0 * 32 + x;
            d =      p[0 * 32] * rh[0];
            d = fmaf(p[1 * 32], rh[1], d);
            d = fmaf(p[2 * 32], rh[2], d);
            d = fmaf(p[3 * 32], rh[3], d);
            d = fmaf(p[4 * 32], rh[4], d);
            d = fmaf(p[5 * 32], rh[5], d);
            d = fmaf(p[6 * 32], rh[6], d);
            d = fmaf(p[7 * 32], rh[7], d);
        } else {
            d = 0.f;
#pragma unroll
            for (int j = 0; j < 8; ++j)
                d = fmaf(xs[mirN(e0 + j) * 32 + x], rh[j], d);
        }
        ds[k * 32 + x] = d;
    }
    __syncthreads();

    float* out = g_lorec + (size_t)img * N * MP;

    // parity of t = parity of ty (step 16)
    if (ty & 1) {
#pragma unroll
        for (int t = ty; t < N; t += 16) {
            const int k0 = (t - 1) >> 1;
            const float* p = ds + k0 * 32 + x;
            float b;
            b =      p[0 * 32] * rh[7];
            b = fmaf(p[1 * 32], rh[5], b);
            b = fmaf(p[2 * 32], rh[3], b);
            b = fmaf(p[3 * 32], rh[1], b);
            if (valid) out[(size_t)t * MP + col] = xs[t * 32 + x] + b;
        }
    } else {
#pragma unroll
        for (int t = ty; t < N; t += 16) {
            const int k0 = t >> 1;
            const float* p = ds + k0 * 32 + x;
            float b;
            b =      p[0 * 32] * rh[6];
            b = fmaf(p[1 * 32], rh[4], b);
            b = fmaf(p[2 * 32], rh[2], b);
            b = fmaf(p[3 * 32], rh[0], b);
            if (valid) out[(size_t)t * MP + col] = xs[t * 32 + x] + b;
        }
    }
}

// ---------------------------------------------------------------------------
// K3: row IDWT. out = A_row(lo_rec) + B_row(2*hi_w).
// Thread u produces outputs t=2u, 2u+1 (identical sa/sd windows),
// stores one coalesced float2.
// ---------------------------------------------------------------------------
__global__ void __launch_bounds__(512) k_row_idwt(float* __restrict__ out)
{
    __shared__ float sa[2][M + 1];
    __shared__ float sd[2][M + 1];
    const int ry  = threadIdx.y;
    const int row = blockIdx.x * 2 + ry;
    const int u   = threadIdx.x;             // 0..255

    const float* ar = g_lorec + (size_t)row * MP;
    const float* dr = g_hi    + (size_t)row * MP;

    sa[ry][u] = ar[u];
    sd[ry][u] = 2.f * dr[u];
    if (u < 3) {
        sa[ry][256 + u] = ar[256 + u];
        sd[ry][256 + u] = 2.f * dr[256 + u];
    }
    __syncthreads();

    const float rl[8] = REC_LO_INIT;
    const float rh[8] = REC_HI_INIT;

    const float a0 = sa[ry][u],     a1 = sa[ry][u + 1];
    const float a2 = sa[ry][u + 2], a3 = sa[ry][u + 3];
    const float d0 = sd[ry][u],     d1 = sd[ry][u + 1];
    const float d2 = sd[ry][u + 2], d3 = sd[ry][u + 3];

    // t = 2u (even): taps rl[6],rl[4],rl[2],rl[0]
    float ev;
    ev =      a0 * rl[6];
    ev = fmaf(a1,  rl[4], ev);
    ev = fmaf(a2,  rl[2], ev);
    ev = fmaf(a3,  rl[0], ev);
    ev = fmaf(d0,  rh[6], ev);
    ev = fmaf(d1,  rh[4], ev);
    ev = fmaf(d2,  rh[2], ev);
    ev = fmaf(d3,  rh[0], ev);

    // t = 2u+1 (odd): taps rl[7],rl[5],rl[3],rl[1]
    float od;
    od =      a0 * rl[7];
    od = fmaf(a1,  rl[5], od);
    od = fmaf(a2,  rl[3], od);
    od = fmaf(a3,  rl[1], od);
    od = fmaf(d0,  rh[7], od);
    od = fmaf(d1,  rh[5], od);
    od = fmaf(d2,  rh[3], od);
    od = fmaf(d3,  rh[1], od);

    float2* o = (float2*)(out + (size_t)row * N);
    o[u] = make_float2(ev, od);
}

// ---------------------------------------------------------------------------
extern "C" void kernel_launch(void* const* d_in, const int* in_sizes, int n_in,
                              void* d_out, int out_size)
{
    const float* data = (const float*)d_in[0];
    float* out = (float*)d_out;
    (void)in_sizes; (void)n_in; (void)out_size;

    const int k2_smem = (N * 32 + M * 32) * (int)sizeof(float);  // 98688 B
    cudaFuncSetAttribute(k_col_fix, cudaFuncAttributeMaxDynamicSharedMemorySize,
                         k2_smem);

    k_row_dwt<<<NROWS / 2, dim3(256, 2)>>>(data);
    k_col_fix<<<dim3((M + 31) / 32, NIMG), dim3(32, 16), k2_smem>>>();
    k_row_idwt<<<NROWS / 2, dim3(256, 2)>>>(out);
}

// round 3
// speedup vs baseline: 1.6769x; 1.2944x over previous
#include <cuda_runtime.h>
#include <stdint.h>

// ---------------------------------------------------------------------------
// extract_high_freq via db4 wavelet, images: [96][512][512] fp32
//   lo_w, hi_w = row-DWT(data)            (m = 259 per row)
//   lo_rec     = lo_w + Bcol(lh)          (lh = col-detail of lo_w)
//   hi_rec     = 2 * hi_w                 (perfect reconstruction)
//   out        = row-IDWT(lo_rec, hi_rec)
// ---------------------------------------------------------------------------

#define N     512
#define M     259          // (512+7)/2
#define MP    288          // padded stride, 1152 B (128B-aligned rows)
#define NIMG  96
#define NROWS (NIMG * N)

#define DL0 (-0.010597401784997278f)
#define DL1 ( 0.032883011666982945f)
#define DL2 ( 0.030841381835986965f)
#define DL3 (-0.18703481171888114f)
#define DL4 (-0.02798376941698385f)
#define DL5 ( 0.6308807679295904f)
#define DL6 ( 0.7148465705525415f)
#define DL7 ( 0.23037781330885523f)

// REC_LO[j] = DEC_LO[7-j] ; REC_HI[j] = (-1)^j * DEC_LO[j]
#define REC_LO_INIT { DL7,  DL6,  DL5,  DL4,  DL3,  DL2,  DL1,  DL0 }
#define REC_HI_INIT { DL0, -DL1,  DL2, -DL3,  DL4, -DL5,  DL6, -DL7 }
// K3 hi taps with the hi_rec = 2*hi_w factor folded in
#define REC_HI2_INIT { 2*DL0, -2*DL1,  2*DL2, -2*DL3,  2*DL4, -2*DL5,  2*DL6, -2*DL7 }

__device__ float g_lo   [(size_t)NIMG * N * MP];
__device__ float g_hi   [(size_t)NIMG * N * MP];
__device__ float g_lorec[(size_t)NIMG * N * MP];

__device__ __forceinline__ int mirN(int i) {
    if (i < 0)  i = -1 - i;
    if (i >= N) i = 2 * N - 1 - i;
    return i;
}

// ---------------------------------------------------------------------------
// K1: row DWT, no smem / no barriers. 4 rows/block, 128 threads per row.
// Thread j loads window x[4j-6 .. 4j+3] straight from global (L1 shares the
// overlap between neighbors) and writes k = 2j, 2j+1 of lo and hi.
// ---------------------------------------------------------------------------
__global__ void __launch_bounds__(512) k_row_dwt(const float* __restrict__ x)
{
    const int j   = threadIdx.x;                      // 0..127
    const int row = blockIdx.x * 4 + threadIdx.y;

    const float* xr = x + (size_t)row * N;
    float* lo = g_lo + (size_t)row * MP;
    float* hi = g_hi + (size_t)row * MP;

    const float rl[8] = REC_LO_INIT;
    const float rh[8] = REC_HI_INIT;

    if (j >= 2) {
        // interior: window indices 4j-6 .. 4j+3, all in [2, 511]
        const float2 w0 = *(const float2*)(xr + 4 * j - 6);
        const float2 w1 = *(const float2*)(xr + 4 * j - 4);
        const float2 w2 = *(const float2*)(xr + 4 * j - 2);
        const float4 w3 = *(const float4*)(xr + 4 * j);

        float win[10] = { w0.x, w0.y, w1.x, w1.y, w2.x, w2.y,
                          w3.x, w3.y, w3.z, w3.w };

        float a0 = 0.f, d0 = 0.f, a1 = 0.f, d1 = 0.f;
#pragma unroll
        for (int i = 0; i < 8; ++i) {
            a0 = fmaf(win[i],     rl[i], a0);
            d0 = fmaf(win[i],     rh[i], d0);
            a1 = fmaf(win[i + 2], rl[i], a1);
            d1 = fmaf(win[i + 2], rh[i], d1);
        }
        *(float2*)(lo + 2 * j) = make_float2(a0, a1);
        *(float2*)(hi + 2 * j) = make_float2(d0, d1);
    } else {
        // left boundary: k = 2j, 2j+1 with mirrored extension
        float av[2], dv[2];
#pragma unroll
        for (int q = 0; q < 2; ++q) {
            const int e0 = 2 * (2 * j + q) - 6;
            float a = 0.f, d = 0.f;
#pragma unroll
            for (int i = 0; i < 8; ++i) {
                const float v = xr[mirN(e0 + i)];
                a = fmaf(v, rl[i], a);
                d = fmaf(v, rh[i], d);
            }
            av[q] = a; dv[q] = d;
        }
        *(float2*)(lo + 2 * j) = make_float2(av[0], av[1]);
        *(float2*)(hi + 2 * j) = make_float2(dv[0], dv[1]);
    }

    // right tail k = 256..258 on threads j = 125..127 (mirrored)
    if (j >= 125) {
        const int kk = j + 131;                       // 256..258
        const int e0 = 2 * kk - 6;
        float a = 0.f, d = 0.f;
#pragma unroll
        for (int i = 0; i < 8; ++i) {
            const float v = xr[mirN(e0 + i)];
            a = fmaf(v, rl[i], a);
            d = fmaf(v, rh[i], d);
        }
        lo[kk] = a;
        hi[kk] = d;
    }
}

// ---------------------------------------------------------------------------
// K2: column correction on lo_w: lo_rec[:,c] = lo_w[:,c] + Bcol(lh[:,c])
// 32 cols x 512 rows per block, 512 threads (32x16), smem stride 32.
// ---------------------------------------------------------------------------
__global__ void __launch_bounds__(512) k_col_fix()
{
    extern __shared__ float sm[];
    float* xs = sm;            // [N][32]
    float* ds = sm + N * 32;   // [M][32]

    const int x   = threadIdx.x;                 // 0..31
    const int ty  = threadIdx.y;                 // 0..15
    const int col = blockIdx.x * 32 + x;
    const int img = blockIdx.y;
    const bool valid = (col < M);

    const float* in = g_lo + (size_t)img * N * MP;

#pragma unroll 4
    for (int r = ty; r < N; r += 16)
        xs[r * 32 + x] = valid ? in[(size_t)r * MP + col] : 0.f;
    __syncthreads();

    const float rh[8] = REC_HI_INIT;

#pragma unroll
    for (int k = ty; k < M; k += 16) {
        const int e0 = 2 * k - 6;
        float d;
        if (k >= 3 && k <= 255) {
            const float* p = xs + e0 * 32 + x;
            d =      p[0 * 32] * rh[0];
            d = fmaf(p[1 * 32], rh[1], d);
            d = fmaf(p[2 * 32], rh[2], d);
            d = fmaf(p[3 * 32], rh[3], d);
            d = fmaf(p[4 * 32], rh[4], d);
            d = fmaf(p[5 * 32], rh[5], d);
            d = fmaf(p[6 * 32], rh[6], d);
            d = fmaf(p[7 * 32], rh[7], d);
        } else {
            d = 0.f;
#pragma unroll
            for (int i = 0; i < 8; ++i)
                d = fmaf(xs[mirN(e0 + i) * 32 + x], rh[i], d);
        }
        ds[k * 32 + x] = d;
    }
    __syncthreads();

    float* out = g_lorec + (size_t)img * N * MP;

    // parity of t = parity of ty (step 16)
    if (ty & 1) {
#pragma unroll
        for (int t = ty; t < N; t += 16) {
            const int k0 = (t - 1) >> 1;
            const float* p = ds + k0 * 32 + x;
            float b;
            b =      p[0 * 32] * rh[7];
            b = fmaf(p[1 * 32], rh[5], b);
            b = fmaf(p[2 * 32], rh[3], b);
            b = fmaf(p[3 * 32], rh[1], b);
            if (valid) out[(size_t)t * MP + col] = xs[t * 32 + x] + b;
        }
    } else {
#pragma unroll
        for (int t = ty; t < N; t += 16) {
            const int k0 = t >> 1;
            const float* p = ds + k0 * 32 + x;
            float b;
            b =      p[0 * 32] * rh[6];
            b = fmaf(p[1 * 32], rh[4], b);
            b = fmaf(p[2 * 32], rh[2], b);
            b = fmaf(p[3 * 32], rh[0], b);
            if (valid) out[(size_t)t * MP + col] = xs[t * 32 + x] + b;
        }
    }
}

// ---------------------------------------------------------------------------
// K3: row IDWT, no smem / no barriers. 4 rows/block, 128 threads per row.
// Thread j loads a[2j..2j+4], d[2j..2j+4] and writes out[4j..4j+3] (STG.128).
// Hi branch x2 folded into taps. All windows interior (no mirroring).
// ---------------------------------------------------------------------------
__global__ void __launch_bounds__(512) k_row_idwt(float* __restrict__ out)
{
    const int j   = threadIdx.x;                      // 0..127
    const int row = blockIdx.x * 4 + threadIdx.y;

    const float* ar = g_lorec + (size_t)row * MP;
    const float* dr = g_hi    + (size_t)row * MP;

    const float rl[8]  = REC_LO_INIT;
    const float rh2[8] = REC_HI2_INIT;

    const float2 a01 = *(const float2*)(ar + 2 * j);
    const float2 a23 = *(const float2*)(ar + 2 * j + 2);
    const float  a4  = ar[2 * j + 4];                 // max idx 258 = M-1
    const float2 d01 = *(const float2*)(dr + 2 * j);
    const float2 d23 = *(const float2*)(dr + 2 * j + 2);
    const float  d4  = dr[2 * j + 4];

    const float a[5] = { a01.x, a01.y, a23.x, a23.y, a4 };
    const float d[5] = { d01.x, d01.y, d23.x, d23.y, d4 };

    float r[4];
#pragma unroll
    for (int q = 0; q < 2; ++q) {                     // u = 2j + q
        // t = 2u (even): taps 6,4,2,0 ; t = 2u+1 (odd): taps 7,5,3,1
        float ev, od;
        ev =      a[q]     * rl[6];
        ev = fmaf(a[q + 1],  rl[4], ev);
        ev = fmaf(a[q + 2],  rl[2], ev);
        ev = fmaf(a[q + 3],  rl[0], ev);
        ev = fmaf(d[q],      rh2[6], ev);
        ev = fmaf(d[q + 1],  rh2[4], ev);
        ev = fmaf(d[q + 2],  rh2[2], ev);
        ev = fmaf(d[q + 3],  rh2[0], ev);

        od =      a[q]     * rl[7];
        od = fmaf(a[q + 1],  rl[5], od);
        od = fmaf(a[q + 2],  rl[3], od);
        od = fmaf(a[q + 3],  rl[1], od);
        od = fmaf(d[q],      rh2[7], od);
        od = fmaf(d[q + 1],  rh2[5], od);
        od = fmaf(d[q + 2],  rh2[3], od);
        od = fmaf(d[q + 3],  rh2[1], od);

        r[2 * q]     = ev;
        r[2 * q + 1] = od;
    }

    *(float4*)(out + (size_t)row * N + 4 * j) = make_float4(r[0], r[1], r[2], r[3]);
}

// ---------------------------------------------------------------------------
extern "C" void kernel_launch(void* const* d_in, const int* in_sizes, int n_in,
                              void* d_out, int out_size)
{
    const float* data = (const float*)d_in[0];
    float* out = (float*)d_out;
    (void)in_sizes; (void)n_in; (void)out_size;

    const int k2_smem = (N * 32 + M * 32) * (int)sizeof(float);  // 98688 B
    cudaFuncSetAttribute(k_col_fix, cudaFuncAttributeMaxDynamicSharedMemorySize,
                         k2_smem);

    k_row_dwt<<<NROWS / 4, dim3(128, 4)>>>(data);
    k_col_fix<<<dim3((M + 31) / 32, NIMG), dim3(32, 16), k2_smem>>>();
    k_row_idwt<<<NROWS / 4, dim3(128, 4)>>>(out);
}